// round 11
// baseline (speedup 1.0000x reference)
#include <cuda_runtime.h>
#include <cuda_fp16.h>
#include <math.h>

// Caps1D dynamic routing — round 11.
// Phase 1 (unchanged): HFMA2 u_ji from prologue-packed fp16 W, 8 coalesced
// LDG.128 per row, u_ji register-resident (40 half2), 2 CTAs/SM.
// Phase 2 restructured:
//  * One __syncthreads per reduction (3 total). Double-buffered smem partials
//    make the single barrier WAR-safe across consecutive reductions.
//  * Redundant per-warp stage-2: every warp sums the 16x16 partial grid,
//    computes 1/Z + squash, and rebuilds vh[8] via in-warp shfl. No serial
//    t<16 section, no vbuf publish barrier.
//  * dot -> exp -> S fused into a single register sweep (5 sweeps -> 3);
//    MUFU.EX2 latency overlaps the fp16 dot chain of the next row.

namespace {
constexpr int T    = 512;
constexpr int Rdim = 2336;
constexpr int Pdim = 16;
constexpr int Kdim = 2;
constexpr int Bdim = 1024;
constexpr int NW   = T / 32;
constexpr int J    = 5;                    // rows per thread
constexpr int WCONV = Kdim * J * 8 * 512;  // int4 elements in packed W
}

// Packed fp16 W: [k][j][c][t] -> int4. c = 2*m + hc; int4 holds 4 half2
// covering p = hc*8 .. hc*8+7 for that m. Rows >= Rdim are zero.
__device__ int4 W2dev[WCONV];

__global__ void convert_w_kernel(const float* __restrict__ W) {
    const int idx = blockIdx.x * blockDim.x + threadIdx.x;
    if (idx >= WCONV) return;
    const int t  = idx & 511;
    const int c  = (idx >> 9) & 7;
    const int kj = idx >> 12;
    const int j  = kj % J;
    const int k  = kj / J;
    const int row = j * 512 + t;
    const int m   = c >> 1;
    const int hc  = c & 1;
    int4 o = make_int4(0, 0, 0, 0);
    if (row < Rdim) {
        const float4* src = reinterpret_cast<const float4*>(W)
                          + ((size_t)(k * Rdim + row) * 4 + m) * 4 + hc * 2;
        float4 a = src[0];
        float4 b = src[1];
        __half2 h0 = __floats2half2_rn(a.x, a.y);
        __half2 h1 = __floats2half2_rn(a.z, a.w);
        __half2 h2 = __floats2half2_rn(b.x, b.y);
        __half2 h3 = __floats2half2_rn(b.z, b.w);
        o.x = *reinterpret_cast<int*>(&h0);
        o.y = *reinterpret_cast<int*>(&h1);
        o.z = *reinterpret_cast<int*>(&h2);
        o.w = *reinterpret_cast<int*>(&h3);
    }
    W2dev[idx] = o;
}

// Dual-accumulator fp16 dot: <h[0..7], vh[0..7]> (16 scalar products).
__device__ __forceinline__ float dot16h(const __half2* hj, const __half2* vh) {
    __half2 a = __hmul2(hj[0], vh[0]);
    __half2 b = __hmul2(hj[1], vh[1]);
    a = __hfma2(hj[2], vh[2], a);  b = __hfma2(hj[3], vh[3], b);
    a = __hfma2(hj[4], vh[4], a);  b = __hfma2(hj[5], vh[5], b);
    a = __hfma2(hj[6], vh[6], a);  b = __hfma2(hj[7], vh[7], b);
    float2 fa = __half22float2(a);
    float2 fb = __half22float2(b);
    return (fa.x + fa.y) + (fb.x + fb.y);
}

__global__ __launch_bounds__(T, 2)
void caps_routing_kernel(const float* __restrict__ u,
                         float* __restrict__ out) {
    // Double-buffered reduction scratch (single barrier per reduction).
    __shared__ __align__(16) float redS[2][NW * Pdim];
    __shared__ float redW[2][NW];

    const int t    = threadIdx.x;
    const int lane = t & 31;
    const int wid  = t >> 5;
    const int l16  = lane & 15;
    const int bid  = blockIdx.x;
    const int b    = bid >> 1;
    const int k    = bid & 1;
    const unsigned F = 0xffffffffu;

    const float4* U4 = reinterpret_cast<const float4*>(u) + (size_t)b * Rdim;

    // ---------------- Phase 1: u_ji -> fp16 registers (HFMA2) ----------------
    __half2 h[J][8];   // h[j][pp] = (p=2pp, p=2pp+1)

    #pragma unroll
    for (int j = 0; j < J; j++) {
        const int row  = j * 512 + t;
        const int rowc = row < Rdim ? row : Rdim - 1;   // clamp; W=0 masks tail
        float4 u4 = U4[rowc];
        __half2 u0 = __float2half2_rn(u4.x);
        __half2 u1 = __float2half2_rn(u4.y);
        __half2 u2 = __float2half2_rn(u4.z);
        __half2 u3 = __float2half2_rn(u4.w);

        const int4* Wp = W2dev + (size_t)(k * J + j) * 8 * 512 + t;
        int4 wa[8];
        #pragma unroll
        for (int c = 0; c < 8; c++) wa[c] = Wp[c * 512];   // 8 coalesced LDG.128
        const __half2* wh = reinterpret_cast<const __half2*>(wa);

        #pragma unroll
        for (int hc = 0; hc < 2; hc++) {
            #pragma unroll
            for (int i = 0; i < 4; i++) {
                __half2 acc = __hmul2(u3, wh[(6 + hc) * 4 + i]);
                acc = __hfma2(u2, wh[(4 + hc) * 4 + i], acc);
                acc = __hfma2(u1, wh[(2 + hc) * 4 + i], acc);
                acc = __hfma2(u0, wh[(0 + hc) * 4 + i], acc);
                h[j][hc * 4 + i] = acc;
            }
        }
    }

    // ---------------- Phase 2: routing ----------------
    float d[J];
    #pragma unroll
    for (int j = 0; j < J; j++) d[j] = (j * 512 + t < Rdim) ? 0.f : -1.0e30f;

    __half2 vh[8];
    float nrm = 0.f;

    // One reduction: s[16] (+ optional lsum->Z). Single __syncthreads.
    // Every warp redundantly computes stage 2 and rebuilds vh[8] via shfl.
    auto reduceSZ = [&](float* s, float lsum, bool use_z, float fixed_pre,
                        int buf, bool need_v) {
        // value-splitting warp butterfly: 16 comps -> 4 per lane-octet
        float r8[8];
        {
            const bool hi = (lane & 16) != 0;
            #pragma unroll
            for (int i = 0; i < 8; i++) {
                float send = hi ? s[i] : s[8 + i];
                float recv = __shfl_xor_sync(F, send, 16);
                r8[i] = (hi ? s[8 + i] : s[i]) + recv;
            }
        }
        float r4[4];
        {
            const bool hi = (lane & 8) != 0;
            #pragma unroll
            for (int i = 0; i < 4; i++) {
                float send = hi ? r8[i] : r8[4 + i];
                float recv = __shfl_xor_sync(F, send, 8);
                r4[i] = (hi ? r8[4 + i] : r8[i]) + recv;
            }
        }
        #pragma unroll
        for (int o = 4; o >= 1; o >>= 1) {
            #pragma unroll
            for (int i = 0; i < 4; i++) r4[i] += __shfl_xor_sync(F, r4[i], o);
        }
        if (use_z) {
            #pragma unroll
            for (int o = 16; o >= 1; o >>= 1) lsum += __shfl_xor_sync(F, lsum, o);
        }
        if ((lane & 7) == 0) {
            const int quad = ((lane >> 4) & 1) * 2 + ((lane >> 3) & 1);
            float4 v4 = make_float4(r4[0], r4[1], r4[2], r4[3]);
            *reinterpret_cast<float4*>(&redS[buf][wid * Pdim + quad * 4]) = v4;
        }
        if (use_z && lane == 0) redW[buf][wid] = lsum;
        __syncthreads();

        // redundant stage 2 in every warp
        float acc = 0.f;
        #pragma unroll
        for (int w = 0; w < NW; ++w) acc += redS[buf][w * Pdim + l16];
        float pre = fixed_pre;
        if (use_z) {
            float Z = 0.f;
            #pragma unroll
            for (int w = 0; w < NW; ++w) Z += redW[buf][w];   // broadcast LDS
            pre = __frcp_rn(Z);
        }
        acc *= pre;
        float nn = acc * acc;
        #pragma unroll
        for (int o = 8; o >= 1; o >>= 1) nn += __shfl_xor_sync(F, nn, o);
        nrm = nn;                                 // valid in all lanes (dup 16..31)
        if (need_v) {
            float vf = sqrtf(nn) / (1.f + nn);
            float vv = acc * vf;
            float vnext = __shfl_xor_sync(F, vv, 1);
            __half2 packed = __floats2half2_rn(vv, vnext);    // valid at even lanes
            unsigned pu = *reinterpret_cast<unsigned*>(&packed);
            #pragma unroll
            for (int i = 0; i < 8; i++) {
                unsigned g = __shfl_sync(F, pu, 2 * i);
                vh[i] = *reinterpret_cast<__half2*>(&g);
            }
        }
    };

    // ---- sweep 0: uniform-c sum ----
    {
        float s[Pdim];
        #pragma unroll
        for (int pp = 0; pp < 8; pp++) {
            __half2 acc = h[0][pp];
            #pragma unroll
            for (int j = 1; j < J; j++) acc = __hadd2(acc, h[j][pp]);  // tail rows 0
            float2 f = __half22float2(acc);
            s[2 * pp]     = f.x;
            s[2 * pp + 1] = f.y;
        }
        reduceSZ(s, 0.f, false, 1.0f / (float)Rdim, 0, true);
    }

    // ---- fused sweeps 1, 2: dot -> exp -> exp-weighted S ----
    #pragma unroll
    for (int it = 1; it < 3; ++it) {
        float s[Pdim];
        #pragma unroll
        for (int p = 0; p < Pdim; p++) s[p] = 0.f;
        float lsum = 0.f;
        #pragma unroll
        for (int j = 0; j < J; j++) {
            float dd = dot16h(h[j], vh);          // tail rows: h=0 -> dd=0
            float dn = d[j] + dd;                 // invalid rows stay -1e30
            d[j] = dn;
            float e = __expf(dn);                 // invalid -> 0
            lsum += e;
            #pragma unroll
            for (int pp = 0; pp < 8; pp++) {
                float2 f = __half22float2(h[j][pp]);
                s[2 * pp]     = fmaf(e, f.x, s[2 * pp]);
                s[2 * pp + 1] = fmaf(e, f.y, s[2 * pp + 1]);
            }
        }
        reduceSZ(s, lsum, true, 0.f, it & 1, it != 2);
    }

    if (t == 0) {
        out[bid] = nrm / (1.f + nrm);
    }
}

extern "C" void kernel_launch(void* const* d_in, const int* in_sizes, int n_in,
                              void* d_out, int out_size) {
    const float* u = (const float*)d_in[0];   // [B, R, M] fp32
    const float* W = (const float*)d_in[1];   // [K, R, M, P] fp32
    float* out = (float*)d_out;               // [B, K] fp32

    convert_w_kernel<<<(WCONV + 255) / 256, 256>>>(W);
    caps_routing_kernel<<<Bdim * Kdim, T>>>(u, out);
}

// round 12
// speedup vs baseline: 1.0567x; 1.0567x over previous
#include <cuda_runtime.h>
#include <cuda_fp16.h>
#include <math.h>

// Caps1D dynamic routing — round 12.
// R10 structure (2 CTAs/SM, warp0-only reduction stage-2) + R11's fused
// dot->exp->S sweep + double-buffered reduction scratch:
//  * 2 __syncthreads per reduction (6 total; was 9). Leading WAR barrier
//    removed by alternating redS/redW/vbufh buffers between reductions.
//  * Phase 2 register sweeps over u_ji: 3 (sweep0 + 2 fused sweeps).
// Phase 1 unchanged: HFMA2 u_ji from prologue-packed fp16 W, 8 coalesced
// LDG.128 per row, u_ji register-resident (40 half2).

namespace {
constexpr int T    = 512;
constexpr int Rdim = 2336;
constexpr int Pdim = 16;
constexpr int Kdim = 2;
constexpr int Bdim = 1024;
constexpr int NW   = T / 32;
constexpr int J    = 5;                    // rows per thread
constexpr int WCONV = Kdim * J * 8 * 512;  // int4 elements in packed W
}

// Packed fp16 W: [k][j][c][t] -> int4. c = 2*m + hc; int4 holds 4 half2
// covering p = hc*8 .. hc*8+7 for that m. Rows >= Rdim are zero.
__device__ int4 W2dev[WCONV];

__global__ void convert_w_kernel(const float* __restrict__ W) {
    const int idx = blockIdx.x * blockDim.x + threadIdx.x;
    if (idx >= WCONV) return;
    const int t  = idx & 511;
    const int c  = (idx >> 9) & 7;
    const int kj = idx >> 12;
    const int j  = kj % J;
    const int k  = kj / J;
    const int row = j * 512 + t;
    const int m   = c >> 1;
    const int hc  = c & 1;
    int4 o = make_int4(0, 0, 0, 0);
    if (row < Rdim) {
        const float4* src = reinterpret_cast<const float4*>(W)
                          + ((size_t)(k * Rdim + row) * 4 + m) * 4 + hc * 2;
        float4 a = src[0];
        float4 b = src[1];
        __half2 h0 = __floats2half2_rn(a.x, a.y);
        __half2 h1 = __floats2half2_rn(a.z, a.w);
        __half2 h2 = __floats2half2_rn(b.x, b.y);
        __half2 h3 = __floats2half2_rn(b.z, b.w);
        o.x = *reinterpret_cast<int*>(&h0);
        o.y = *reinterpret_cast<int*>(&h1);
        o.z = *reinterpret_cast<int*>(&h2);
        o.w = *reinterpret_cast<int*>(&h3);
    }
    W2dev[idx] = o;
}

// Dual-accumulator fp16 dot: <h[0..7], vh[0..7]> (16 scalar products).
__device__ __forceinline__ float dot16h(const __half2* hj, const __half2* vh) {
    __half2 a = __hmul2(hj[0], vh[0]);
    __half2 b = __hmul2(hj[1], vh[1]);
    a = __hfma2(hj[2], vh[2], a);  b = __hfma2(hj[3], vh[3], b);
    a = __hfma2(hj[4], vh[4], a);  b = __hfma2(hj[5], vh[5], b);
    a = __hfma2(hj[6], vh[6], a);  b = __hfma2(hj[7], vh[7], b);
    float2 fa = __half22float2(a);
    float2 fb = __half22float2(b);
    return (fa.x + fa.y) + (fb.x + fb.y);
}

__global__ __launch_bounds__(T, 2)
void caps_routing_kernel(const float* __restrict__ u,
                         float* __restrict__ out) {
    // Double-buffered reduction scratch: 2 barriers per reduction.
    __shared__ __align__(16) float redS[2][NW * Pdim];
    __shared__ float   redW[2][NW];
    __shared__ __half2 vbufh[2][Pdim / 2];
    __shared__ float   miscS;

    const int t    = threadIdx.x;
    const int lane = t & 31;
    const int wid  = t >> 5;
    const int bid  = blockIdx.x;
    const int b    = bid >> 1;
    const int k    = bid & 1;
    const unsigned F = 0xffffffffu;

    const float4* U4 = reinterpret_cast<const float4*>(u) + (size_t)b * Rdim;

    // ---------------- Phase 1: u_ji -> fp16 registers (HFMA2) ----------------
    __half2 h[J][8];   // h[j][pp] = (p=2pp, p=2pp+1)

    #pragma unroll
    for (int j = 0; j < J; j++) {
        const int row  = j * 512 + t;
        const int rowc = row < Rdim ? row : Rdim - 1;   // clamp; W=0 masks tail
        float4 u4 = U4[rowc];
        __half2 u0 = __float2half2_rn(u4.x);
        __half2 u1 = __float2half2_rn(u4.y);
        __half2 u2 = __float2half2_rn(u4.z);
        __half2 u3 = __float2half2_rn(u4.w);

        const int4* Wp = W2dev + (size_t)(k * J + j) * 8 * 512 + t;
        int4 wa[8];
        #pragma unroll
        for (int c = 0; c < 8; c++) wa[c] = Wp[c * 512];   // 8 coalesced LDG.128
        const __half2* wh = reinterpret_cast<const __half2*>(wa);

        #pragma unroll
        for (int hc = 0; hc < 2; hc++) {
            #pragma unroll
            for (int i = 0; i < 4; i++) {
                __half2 acc = __hmul2(u3, wh[(6 + hc) * 4 + i]);
                acc = __hfma2(u2, wh[(4 + hc) * 4 + i], acc);
                acc = __hfma2(u1, wh[(2 + hc) * 4 + i], acc);
                acc = __hfma2(u0, wh[(0 + hc) * 4 + i], acc);
                h[j][hc * 4 + i] = acc;
            }
        }
    }

    // ---------------- Phase 2: routing (lane-local rows) ----------------
    float d[J];
    #pragma unroll
    for (int j = 0; j < J; j++) d[j] = (j * 512 + t < Rdim) ? 0.f : -1.0e30f;

    __half2 vh[8];

    // One reduction: S[16] (+ optional Z) -> squash -> v published to
    // vbufh[buf] by warp 0 only. Exactly two __syncthreads.
    auto reduceSZ = [&](float* s, float lsum, bool use_z, float fixed_pre,
                        int buf, bool need_v) {
        float r8[8];
        {
            const bool hi = (lane & 16) != 0;
            #pragma unroll
            for (int i = 0; i < 8; i++) {
                float send = hi ? s[i] : s[8 + i];
                float recv = __shfl_xor_sync(F, send, 16);
                r8[i] = (hi ? s[8 + i] : s[i]) + recv;
            }
        }
        float r4[4];
        {
            const bool hi = (lane & 8) != 0;
            #pragma unroll
            for (int i = 0; i < 4; i++) {
                float send = hi ? r8[i] : r8[4 + i];
                float recv = __shfl_xor_sync(F, send, 8);
                r4[i] = (hi ? r8[4 + i] : r8[i]) + recv;
            }
        }
        #pragma unroll
        for (int o = 4; o >= 1; o >>= 1) {
            #pragma unroll
            for (int i = 0; i < 4; i++) r4[i] += __shfl_xor_sync(F, r4[i], o);
        }
        if (use_z) {
            #pragma unroll
            for (int o = 16; o >= 1; o >>= 1) lsum += __shfl_xor_sync(F, lsum, o);
        }
        if ((lane & 7) == 0) {
            const int quad = ((lane >> 4) & 1) * 2 + ((lane >> 3) & 1);
            float4 v4 = make_float4(r4[0], r4[1], r4[2], r4[3]);
            *reinterpret_cast<float4*>(&redS[buf][wid * Pdim + quad * 4]) = v4;
        }
        if (use_z && lane == 0) redW[buf][wid] = lsum;
        __syncthreads();

        if (t < Pdim) {   // warp 0 lanes 0..15 only
            float acc = 0.f;
            #pragma unroll
            for (int w = 0; w < NW; ++w) acc += redS[buf][w * Pdim + t];
            float pre = fixed_pre;
            if (use_z) {
                float Z = 0.f;
                #pragma unroll
                for (int w = 0; w < NW; ++w) Z += redW[buf][w];
                pre = __frcp_rn(Z);
            }
            acc *= pre;
            float nn = acc * acc;
            #pragma unroll
            for (int o = 8; o >= 1; o >>= 1) nn += __shfl_xor_sync(0x0000ffffu, nn, o);
            if (need_v) {
                float vf = sqrtf(nn) / (1.f + nn);
                float vv = acc * vf;
                float partner = __shfl_xor_sync(0x0000ffffu, vv, 1);
                if ((t & 1) == 0) vbufh[buf][t >> 1] = __floats2half2_rn(vv, partner);
            }
            if (t == 0) miscS = nn;
        }
        __syncthreads();
    };

    // ---- sweep 0: uniform-c sum ----
    {
        float s[Pdim];
        #pragma unroll
        for (int pp = 0; pp < 8; pp++) {
            __half2 acc = h[0][pp];
            #pragma unroll
            for (int j = 1; j < J; j++) acc = __hadd2(acc, h[j][pp]);  // tail rows 0
            float2 f = __half22float2(acc);
            s[2 * pp]     = f.x;
            s[2 * pp + 1] = f.y;
        }
        reduceSZ(s, 0.f, false, 1.0f / (float)Rdim, 0, true);
        #pragma unroll
        for (int pp = 0; pp < 8; pp++) vh[pp] = vbufh[0][pp];
    }

    // ---- fused sweeps 1, 2: dot -> exp -> exp-weighted S ----
    #pragma unroll
    for (int it = 1; it < 3; ++it) {
        float s[Pdim];
        #pragma unroll
        for (int p = 0; p < Pdim; p++) s[p] = 0.f;
        float lsum = 0.f;
        #pragma unroll
        for (int j = 0; j < J; j++) {
            float dd = dot16h(h[j], vh);          // tail rows: h=0 -> dd=0
            float dn = d[j] + dd;                 // invalid rows stay -1e30
            d[j] = dn;
            float e = __expf(dn);                 // invalid -> 0
            lsum += e;
            #pragma unroll
            for (int pp = 0; pp < 8; pp++) {
                float2 f = __half22float2(h[j][pp]);
                s[2 * pp]     = fmaf(e, f.x, s[2 * pp]);
                s[2 * pp + 1] = fmaf(e, f.y, s[2 * pp + 1]);
            }
        }
        const int buf = it & 1;                   // r1 -> buf1, r2 -> buf0
        reduceSZ(s, lsum, true, 0.f, buf, it != 2);
        if (it != 2) {
            #pragma unroll
            for (int pp = 0; pp < 8; pp++) vh[pp] = vbufh[buf][pp];
        }
    }

    if (t == 0) {
        const float nrm = miscS;
        out[bid] = nrm / (1.f + nrm);
    }
}

extern "C" void kernel_launch(void* const* d_in, const int* in_sizes, int n_in,
                              void* d_out, int out_size) {
    const float* u = (const float*)d_in[0];   // [B, R, M] fp32
    const float* W = (const float*)d_in[1];   // [K, R, M, P] fp32
    float* out = (float*)d_out;               // [B, K] fp32

    convert_w_kernel<<<(WCONV + 255) / 256, 256>>>(W);
    caps_routing_kernel<<<Bdim * Kdim, T>>>(u, out);
}